// round 5
// baseline (speedup 1.0000x reference)
#include <cuda_runtime.h>

#define ND 50000
#define EE 1600000
#define DD 128

// ---------------- scratch (device globals: alloc-free) ----------------
__device__ int   g_outdeg[ND];
__device__ int   g_indeg[ND];
__device__ float g_norm_out[ND];
__device__ float g_norm_in[ND];
__device__ int   g_row_ptr[ND + 1];
__device__ int   g_cursor[ND];
__device__ int   g_csr_src[EE];
__device__ float g_Xs[(size_t)ND * DD];  // norm_out-scaled input features
__device__ float g_H[(size_t)ND * DD];   // norm_out-scaled hidden after conv1
__device__ float g_z1[128];              // [1,100] accumulator (padded)

// ---------------- K1: zero small scratch ----------------
__global__ void k_zero(int nodes) {
    int i = blockIdx.x * blockDim.x + threadIdx.x;
    int stride = gridDim.x * blockDim.x;
    for (int j = i; j < nodes; j += stride) {
        g_outdeg[j] = 0;
        g_indeg[j] = 0;
    }
    if (i < 128) g_z1[i] = 0.f;
}

// ---------------- K2: integer degrees ----------------
__global__ void k_degree(const int* __restrict__ src, const int* __restrict__ dst, int E) {
    int i = blockIdx.x * blockDim.x + threadIdx.x;
    int stride = gridDim.x * blockDim.x;
    for (int e = i; e < E; e += stride) {
        atomicAdd(&g_outdeg[src[e]], 1);
        atomicAdd(&g_indeg[dst[e]], 1);
    }
}

// ---------------- K3: norms + exclusive scan of in-degree -> row_ptr ----------------
__global__ void __launch_bounds__(1024) k_scan(int nodes) {
    __shared__ int ssum[1024];
    int t = threadIdx.x;
    int chunk = (nodes + 1023) / 1024;
    int begin = t * chunk;
    int end = begin + chunk; if (end > nodes) end = nodes;
    if (begin > nodes) begin = nodes;

    int s = 0;
    for (int i = begin; i < end; i++) s += g_indeg[i];
    ssum[t] = s;
    __syncthreads();
    #pragma unroll
    for (int off = 1; off < 1024; off <<= 1) {
        int v = (t >= off) ? ssum[t - off] : 0;
        __syncthreads();
        ssum[t] += v;
        __syncthreads();
    }
    int run = ssum[t] - s;  // exclusive prefix
    for (int i = begin; i < end; i++) {
        g_row_ptr[i] = run;
        g_cursor[i] = run;
        run += g_indeg[i];
        g_norm_out[i] = rsqrtf(fmaxf((float)g_outdeg[i], 1.f));
        g_norm_in[i]  = rsqrtf(fmaxf((float)g_indeg[i], 1.f));
    }
    if (t == 1023) g_row_ptr[nodes] = ssum[1023];
}

// ---------------- K4: CSR fill (bucket src by dst) ----------------
__global__ void k_fill(const int* __restrict__ src, const int* __restrict__ dst, int E) {
    int i = blockIdx.x * blockDim.x + threadIdx.x;
    int stride = gridDim.x * blockDim.x;
    for (int e = i; e < E; e += stride) {
        int pos = atomicAdd(&g_cursor[dst[e]], 1);
        g_csr_src[pos] = src[e];
    }
}

// ---------------- K4b: pre-scale x by norm_out ----------------
__global__ void k_prescale(const float4* __restrict__ X, int nodes) {
    int warp = (blockIdx.x * blockDim.x + threadIdx.x) >> 5;
    int nw = (gridDim.x * blockDim.x) >> 5;
    int lane = threadIdx.x & 31;
    float4* Xs4 = (float4*)g_Xs;
    for (int i = warp; i < nodes; i += nw) {
        float ns = g_norm_out[i];
        float4 v = __ldg(&X[(size_t)i * 32 + lane]);
        v.x *= ns; v.y *= ns; v.z *= ns; v.w *= ns;
        Xs4[(size_t)i * 32 + lane] = v;
    }
}

// ---------------- high-MLP warp gather: sum of pre-scaled feature rows ----------------
// acc = norm_in[node] * sum_{s in in(node)} F[s][lane]   (F already norm_out-scaled)
__device__ __forceinline__ float4 agg_node_warp(const float4* __restrict__ F, int node,
                                                int nodes, int lane) {
    float4 acc = make_float4(0.f, 0.f, 0.f, 0.f);
    if (node >= nodes) return acc;
    int beg = g_row_ptr[node];
    int end = g_row_ptr[node + 1];
    for (int base = beg; base < end; base += 32) {
        int rem = end - base;
        int idx = 0;
        bool valid = lane < rem;
        if (valid) idx = __ldg(&g_csr_src[base + lane]);
        if (rem >= 32) {
            #pragma unroll
            for (int e = 0; e < 32; e++) {
                int s = __shfl_sync(0xFFFFFFFFu, idx, e);
                float4 v = __ldg(&F[(size_t)s * 32 + lane]);
                acc.x += v.x; acc.y += v.y; acc.z += v.z; acc.w += v.w;
            }
        } else {
            #pragma unroll 4
            for (int e = 0; e < rem; e++) {
                int s = __shfl_sync(0xFFFFFFFFu, idx, e);
                float4 v = __ldg(&F[(size_t)s * 32 + lane]);
                acc.x += v.x; acc.y += v.y; acc.z += v.z; acc.w += v.w;
            }
        }
    }
    float ni = g_norm_in[node];
    acc.x *= ni; acc.y *= ni; acc.z *= ni; acc.w *= ni;
    return acc;
}

// ---------------- K5: conv1 = agg + GEMM + bias + leaky, write norm_out-scaled H ----------------
__global__ void __launch_bounds__(256) k_conv1(const float* __restrict__ W,
                                               const float* __restrict__ b,
                                               int nodes) {
    __shared__ float As[32 * 128];
    int t = threadIdx.x;
    int lane = t & 31;
    int warp = t >> 5;
    int block_row = blockIdx.x * 32;

    float4* As4 = (float4*)As;
    const float4* Xs4 = (const float4*)g_Xs;
    #pragma unroll
    for (int i = 0; i < 4; i++) {
        int node = block_row + warp * 4 + i;
        As4[(warp * 4 + i) * 32 + lane] = agg_node_warp(Xs4, node, nodes, lane);
    }
    __syncthreads();

    int cr = t & 31;
    int rr = t >> 5;
    float acc[4][4];
    #pragma unroll
    for (int i = 0; i < 4; i++)
        #pragma unroll
        for (int j = 0; j < 4; j++) acc[i][j] = 0.f;

    const float4* W4 = (const float4*)W;
    #pragma unroll 4
    for (int k = 0; k < 128; k++) {
        float4 w = __ldg(&W4[k * 32 + cr]);
        float a0 = As[(rr * 4 + 0) * 128 + k];
        float a1 = As[(rr * 4 + 1) * 128 + k];
        float a2 = As[(rr * 4 + 2) * 128 + k];
        float a3 = As[(rr * 4 + 3) * 128 + k];
        acc[0][0] += a0 * w.x; acc[0][1] += a0 * w.y; acc[0][2] += a0 * w.z; acc[0][3] += a0 * w.w;
        acc[1][0] += a1 * w.x; acc[1][1] += a1 * w.y; acc[1][2] += a1 * w.z; acc[1][3] += a1 * w.w;
        acc[2][0] += a2 * w.x; acc[2][1] += a2 * w.y; acc[2][2] += a2 * w.z; acc[2][3] += a2 * w.w;
        acc[3][0] += a3 * w.x; acc[3][1] += a3 * w.y; acc[3][2] += a3 * w.z; acc[3][3] += a3 * w.w;
    }

    float4 bv = __ldg(&((const float4*)b)[cr]);
    float4* H4 = (float4*)g_H;
    #pragma unroll
    for (int r = 0; r < 4; r++) {
        int row = block_row + rr * 4 + r;
        if (row < nodes) {
            float no = g_norm_out[row];   // pre-scale H for conv2's gather
            float4 o;
            o.x = acc[r][0] + bv.x; o.y = acc[r][1] + bv.y;
            o.z = acc[r][2] + bv.z; o.w = acc[r][3] + bv.w;
            o.x = (o.x >= 0.f ? o.x : 0.01f * o.x) * no;
            o.y = (o.y >= 0.f ? o.y : 0.01f * o.y) * no;
            o.z = (o.z >= 0.f ? o.z : 0.01f * o.z) * no;
            o.w = (o.w >= 0.f ? o.w : 0.01f * o.w) * no;
            H4[(size_t)row * 32 + cr] = o;
        }
    }
}

// ---------------- K6: conv2 + agg_w dot + [1,N]@d1_w partials ----------------
__global__ void __launch_bounds__(256) k_conv2_head(const float* __restrict__ W,
                                                    const float* __restrict__ b,
                                                    const float* __restrict__ agg_w,
                                                    const float* __restrict__ agg_b,
                                                    const float* __restrict__ d1_w,
                                                    int nodes) {
    __shared__ float As[32 * 128];
    __shared__ float s_sm[32];
    int t = threadIdx.x;
    int lane = t & 31;
    int warp = t >> 5;
    int block_row = blockIdx.x * 32;
    int rows = nodes - block_row; if (rows > 32) rows = 32;

    if (t < 32) s_sm[t] = 0.f;

    float4* As4 = (float4*)As;
    const float4* H4c = (const float4*)g_H;
    #pragma unroll
    for (int i = 0; i < 4; i++) {
        int node = block_row + warp * 4 + i;
        As4[(warp * 4 + i) * 32 + lane] = agg_node_warp(H4c, node, nodes, lane);
    }
    __syncthreads();

    int cr = t & 31;
    int rr = t >> 5;
    float acc[4][4];
    #pragma unroll
    for (int i = 0; i < 4; i++)
        #pragma unroll
        for (int j = 0; j < 4; j++) acc[i][j] = 0.f;

    const float4* W4 = (const float4*)W;
    #pragma unroll 4
    for (int k = 0; k < 128; k++) {
        float4 w = __ldg(&W4[k * 32 + cr]);
        float a0 = As[(rr * 4 + 0) * 128 + k];
        float a1 = As[(rr * 4 + 1) * 128 + k];
        float a2 = As[(rr * 4 + 2) * 128 + k];
        float a3 = As[(rr * 4 + 3) * 128 + k];
        acc[0][0] += a0 * w.x; acc[0][1] += a0 * w.y; acc[0][2] += a0 * w.z; acc[0][3] += a0 * w.w;
        acc[1][0] += a1 * w.x; acc[1][1] += a1 * w.y; acc[1][2] += a1 * w.z; acc[1][3] += a1 * w.w;
        acc[2][0] += a2 * w.x; acc[2][1] += a2 * w.y; acc[2][2] += a2 * w.z; acc[2][3] += a2 * w.w;
        acc[3][0] += a3 * w.x; acc[3][1] += a3 * w.y; acc[3][2] += a3 * w.z; acc[3][3] += a3 * w.w;
    }

    // s[row] = (h2_row + b) . agg_w
    float4 bv = __ldg(&((const float4*)b)[cr]);
    float4 aw = __ldg(&((const float4*)agg_w)[cr]);
    #pragma unroll
    for (int r = 0; r < 4; r++) {
        float part = (acc[r][0] + bv.x) * aw.x + (acc[r][1] + bv.y) * aw.y
                   + (acc[r][2] + bv.z) * aw.z + (acc[r][3] + bv.w) * aw.w;
        atomicAdd(&s_sm[rr * 4 + r], part);
    }
    __syncthreads();

    // z1[j] += sum_r (s[row]+agg_b) * d1_w[row*100 + j]
    float ab = __ldg(agg_b);
    if (t < 100) {
        float zacc = 0.f;
        for (int r = 0; r < rows; r++) {
            int row = block_row + r;
            zacc += (s_sm[r] + ab) * __ldg(&d1_w[(size_t)row * 100 + t]);
        }
        atomicAdd(&g_z1[t], zacc);
    }
}

// ---------------- K7: tiny MLP tail ----------------
__global__ void k_tail(const float* __restrict__ d1_b,
                       const float* __restrict__ d2_w, const float* __restrict__ d2_b,
                       const float* __restrict__ d3_w, const float* __restrict__ d3_b,
                       float* __restrict__ out) {
    __shared__ float a[100];
    __shared__ float z2[20];
    int t = threadIdx.x;
    if (t < 100) a[t] = g_z1[t] + d1_b[t];
    __syncthreads();
    if (t < 20) {
        float s = d2_b[t];
        #pragma unroll 4
        for (int j = 0; j < 100; j++) s += a[j] * d2_w[j * 20 + t];
        z2[t] = s >= 0.f ? s : 0.01f * s;
    }
    __syncthreads();
    if (t < 10) {
        float s = d3_b[t];
        #pragma unroll
        for (int m = 0; m < 20; m++) s += z2[m] * d3_w[m * 10 + t];
        out[t] = s;
    }
}

// ---------------- launch ----------------
extern "C" void kernel_launch(void* const* d_in, const int* in_sizes, int n_in,
                              void* d_out, int out_size) {
    const float* x     = (const float*)d_in[0];
    const int*   src   = (const int*)d_in[1];
    const int*   dst   = (const int*)d_in[2];
    const float* W1    = (const float*)d_in[3];
    const float* b1    = (const float*)d_in[4];
    const float* W2    = (const float*)d_in[5];
    const float* b2    = (const float*)d_in[6];
    const float* agg_w = (const float*)d_in[7];
    const float* agg_b = (const float*)d_in[8];
    const float* d1_w  = (const float*)d_in[9];
    const float* d1_b  = (const float*)d_in[10];
    const float* d2_w  = (const float*)d_in[11];
    const float* d2_b  = (const float*)d_in[12];
    const float* d3_w  = (const float*)d_in[13];
    const float* d3_b  = (const float*)d_in[14];

    int nodes = in_sizes[0] / DD;
    int E = in_sizes[1];
    float* out = (float*)d_out;

    int gb = (nodes + 31) / 32;

    k_zero<<<(nodes + 255) / 256, 256>>>(nodes);
    k_degree<<<1024, 256>>>(src, dst, E);
    k_scan<<<1, 1024>>>(nodes);
    k_fill<<<1024, 256>>>(src, dst, E);
    k_prescale<<<1024, 256>>>((const float4*)x, nodes);
    k_conv1<<<gb, 256>>>(W1, b1, nodes);
    k_conv2_head<<<gb, 256>>>(W2, b2, agg_w, agg_b, d1_w, nodes);
    k_tail<<<1, 128>>>(d1_b, d2_w, d2_b, d3_w, d3_b, out);
}

// round 14
// speedup vs baseline: 1.0744x; 1.0744x over previous
#include <cuda_runtime.h>
#include <cuda_fp16.h>

#define ND 50000
#define EE 1600000
#define DD 128

// ---------------- scratch (device globals: alloc-free) ----------------
__device__ int   g_outdeg[ND];
__device__ int   g_indeg[ND];
__device__ float g_norm_out[ND];
__device__ float g_norm_in[ND];
__device__ int   g_row_ptr[ND + 1];
__device__ int   g_cursor[ND];
__device__ int   g_csr_src[EE];
__device__ __half g_Xh[(size_t)ND * DD];  // norm_out-scaled input features (fp16)
__device__ __half g_Hh[(size_t)ND * DD];  // norm_out-scaled hidden (fp16)
__device__ float  g_A[(size_t)ND * DD];   // aggregated rows (fp32, norm_in applied)
__device__ float  g_z1[128];              // [1,100] accumulator (padded)

// ---------------- K1: zero small scratch ----------------
__global__ void k_zero(int nodes) {
    int i = blockIdx.x * blockDim.x + threadIdx.x;
    int stride = gridDim.x * blockDim.x;
    for (int j = i; j < nodes; j += stride) {
        g_outdeg[j] = 0;
        g_indeg[j] = 0;
    }
    if (i < 128) g_z1[i] = 0.f;
}

// ---------------- K2: integer degrees ----------------
__global__ void k_degree(const int* __restrict__ src, const int* __restrict__ dst, int E) {
    int i = blockIdx.x * blockDim.x + threadIdx.x;
    int stride = gridDim.x * blockDim.x;
    for (int e = i; e < E; e += stride) {
        atomicAdd(&g_outdeg[src[e]], 1);
        atomicAdd(&g_indeg[dst[e]], 1);
    }
}

// ---------------- K3: norms + exclusive scan of in-degree -> row_ptr ----------------
__global__ void __launch_bounds__(1024) k_scan(int nodes) {
    __shared__ int ssum[1024];
    int t = threadIdx.x;
    int chunk = (nodes + 1023) / 1024;
    int begin = t * chunk;
    int end = begin + chunk; if (end > nodes) end = nodes;
    if (begin > nodes) begin = nodes;

    int s = 0;
    for (int i = begin; i < end; i++) s += g_indeg[i];
    ssum[t] = s;
    __syncthreads();
    #pragma unroll
    for (int off = 1; off < 1024; off <<= 1) {
        int v = (t >= off) ? ssum[t - off] : 0;
        __syncthreads();
        ssum[t] += v;
        __syncthreads();
    }
    int run = ssum[t] - s;  // exclusive prefix
    for (int i = begin; i < end; i++) {
        g_row_ptr[i] = run;
        g_cursor[i] = run;
        run += g_indeg[i];
        g_norm_out[i] = rsqrtf(fmaxf((float)g_outdeg[i], 1.f));
        g_norm_in[i]  = rsqrtf(fmaxf((float)g_indeg[i], 1.f));
    }
    if (t == 1023) g_row_ptr[nodes] = ssum[1023];
}

// ---------------- K4: CSR fill (bucket src by dst) ----------------
__global__ void k_fill(const int* __restrict__ src, const int* __restrict__ dst, int E) {
    int i = blockIdx.x * blockDim.x + threadIdx.x;
    int stride = gridDim.x * blockDim.x;
    for (int e = i; e < E; e += stride) {
        int pos = atomicAdd(&g_cursor[dst[e]], 1);
        g_csr_src[pos] = src[e];
    }
}

// ---------------- K5: pre-scale x by norm_out -> fp16 ----------------
__global__ void k_prescale(const float4* __restrict__ X, int nodes) {
    int warp = (blockIdx.x * blockDim.x + threadIdx.x) >> 5;
    int nw = (gridDim.x * blockDim.x) >> 5;
    int lane = threadIdx.x & 31;
    uint2* Xh2 = (uint2*)g_Xh;
    for (int i = warp; i < nodes; i += nw) {
        float ns = g_norm_out[i];
        float4 v = __ldg(&X[(size_t)i * 32 + lane]);
        __half2 h0 = __float22half2_rn(make_float2(v.x * ns, v.y * ns));
        __half2 h1 = __float22half2_rn(make_float2(v.z * ns, v.w * ns));
        uint2 o;
        o.x = *(unsigned*)&h0;
        o.y = *(unsigned*)&h1;
        Xh2[(size_t)i * 32 + lane] = o;
    }
}

// ---------------- K6/K8: dedicated gather (warp per node, no atomics) ----------------
// A[node] = norm_in[node] * sum_{s in in(node)} Fh[s]   (Fh already norm_out-scaled)
// NOTE: feature buffer selected INSIDE device code (device-global addresses are
// not valid as host-side kernel arguments).
__global__ void __launch_bounds__(256) k_gather(int from_h, int nodes) {
    const uint2* Fh = from_h ? (const uint2*)g_Hh : (const uint2*)g_Xh;
    int warp = (blockIdx.x * blockDim.x + threadIdx.x) >> 5;
    int lane = threadIdx.x & 31;
    if (warp >= nodes) return;
    int beg = g_row_ptr[warp];
    int end = g_row_ptr[warp + 1];

    float ax = 0.f, ay = 0.f, az = 0.f, aw = 0.f;
    for (int base = beg; base < end; base += 32) {
        int rem = end - base;
        int idx = (lane < rem) ? __ldg(&g_csr_src[base + lane]) : 0;
        if (rem >= 32) {
            #pragma unroll
            for (int e = 0; e < 32; e++) {
                int s = __shfl_sync(0xFFFFFFFFu, idx, e);
                uint2 v = __ldg(&Fh[(size_t)s * 32 + lane]);
                __half2 h0 = *(__half2*)&v.x;
                __half2 h1 = *(__half2*)&v.y;
                float2 f0 = __half22float2(h0);
                float2 f1 = __half22float2(h1);
                ax += f0.x; ay += f0.y; az += f1.x; aw += f1.y;
            }
        } else {
            #pragma unroll 4
            for (int e = 0; e < rem; e++) {
                int s = __shfl_sync(0xFFFFFFFFu, idx, e);
                uint2 v = __ldg(&Fh[(size_t)s * 32 + lane]);
                __half2 h0 = *(__half2*)&v.x;
                __half2 h1 = *(__half2*)&v.y;
                float2 f0 = __half22float2(h0);
                float2 f1 = __half22float2(h1);
                ax += f0.x; ay += f0.y; az += f1.x; aw += f1.y;
            }
        }
    }
    float ni = g_norm_in[warp];
    ((float4*)g_A)[(size_t)warp * 32 + lane] =
        make_float4(ax * ni, ay * ni, az * ni, aw * ni);
}

// ---------------- K7: GEMM1: Hh = norm_out * leaky(A @ W1 + b1) (fp16) ----------------
__global__ void __launch_bounds__(256) k_gemm1(const float* __restrict__ W,
                                               const float* __restrict__ b,
                                               int nodes) {
    __shared__ float As[32 * 128];
    int t = threadIdx.x;
    int block_row = blockIdx.x * 32;
    int rows = nodes - block_row; if (rows > 32) rows = 32;

    const float4* A4 = (const float4*)g_A;
    float4* As4 = (float4*)As;
    for (int idx = t; idx < 32 * 32; idx += 256) {
        int r = idx >> 5;
        float4 v = make_float4(0.f, 0.f, 0.f, 0.f);
        if (r < rows) v = A4[(size_t)(block_row + r) * 32 + (idx & 31)];
        As4[idx] = v;
    }
    __syncthreads();

    int cr = t & 31;
    int rr = t >> 5;
    float acc[4][4];
    #pragma unroll
    for (int i = 0; i < 4; i++)
        #pragma unroll
        for (int j = 0; j < 4; j++) acc[i][j] = 0.f;

    const float4* W4 = (const float4*)W;
    #pragma unroll 4
    for (int k = 0; k < 128; k++) {
        float4 w = __ldg(&W4[k * 32 + cr]);
        float a0 = As[(rr * 4 + 0) * 128 + k];
        float a1 = As[(rr * 4 + 1) * 128 + k];
        float a2 = As[(rr * 4 + 2) * 128 + k];
        float a3 = As[(rr * 4 + 3) * 128 + k];
        acc[0][0] += a0 * w.x; acc[0][1] += a0 * w.y; acc[0][2] += a0 * w.z; acc[0][3] += a0 * w.w;
        acc[1][0] += a1 * w.x; acc[1][1] += a1 * w.y; acc[1][2] += a1 * w.z; acc[1][3] += a1 * w.w;
        acc[2][0] += a2 * w.x; acc[2][1] += a2 * w.y; acc[2][2] += a2 * w.z; acc[2][3] += a2 * w.w;
        acc[3][0] += a3 * w.x; acc[3][1] += a3 * w.y; acc[3][2] += a3 * w.z; acc[3][3] += a3 * w.w;
    }

    float4 bv = __ldg(&((const float4*)b)[cr]);
    uint2* Hh2 = (uint2*)g_Hh;
    #pragma unroll
    for (int r = 0; r < 4; r++) {
        int row = block_row + rr * 4 + r;
        if (row < nodes) {
            float no = g_norm_out[row];   // pre-scale for conv2's gather
            float ox = acc[r][0] + bv.x, oy = acc[r][1] + bv.y;
            float oz = acc[r][2] + bv.z, ow = acc[r][3] + bv.w;
            ox = (ox >= 0.f ? ox : 0.01f * ox) * no;
            oy = (oy >= 0.f ? oy : 0.01f * oy) * no;
            oz = (oz >= 0.f ? oz : 0.01f * oz) * no;
            ow = (ow >= 0.f ? ow : 0.01f * ow) * no;
            __half2 h0 = __float22half2_rn(make_float2(ox, oy));
            __half2 h1 = __float22half2_rn(make_float2(oz, ow));
            uint2 o;
            o.x = *(unsigned*)&h0;
            o.y = *(unsigned*)&h1;
            Hh2[(size_t)row * 32 + cr] = o;
        }
    }
}

// ---------------- K9: GEMM2 + agg_w dot + [1,N]@d1_w partials ----------------
__global__ void __launch_bounds__(256) k_gemm2_head(const float* __restrict__ W,
                                                    const float* __restrict__ b,
                                                    const float* __restrict__ agg_w,
                                                    const float* __restrict__ agg_b,
                                                    const float* __restrict__ d1_w,
                                                    int nodes) {
    __shared__ float As[32 * 128];
    __shared__ float s_sm[32];
    int t = threadIdx.x;
    int block_row = blockIdx.x * 32;
    int rows = nodes - block_row; if (rows > 32) rows = 32;

    if (t < 32) s_sm[t] = 0.f;

    const float4* A4 = (const float4*)g_A;
    float4* As4 = (float4*)As;
    for (int idx = t; idx < 32 * 32; idx += 256) {
        int r = idx >> 5;
        float4 v = make_float4(0.f, 0.f, 0.f, 0.f);
        if (r < rows) v = A4[(size_t)(block_row + r) * 32 + (idx & 31)];
        As4[idx] = v;
    }
    __syncthreads();

    int cr = t & 31;
    int rr = t >> 5;
    float acc[4][4];
    #pragma unroll
    for (int i = 0; i < 4; i++)
        #pragma unroll
        for (int j = 0; j < 4; j++) acc[i][j] = 0.f;

    const float4* W4 = (const float4*)W;
    #pragma unroll 4
    for (int k = 0; k < 128; k++) {
        float4 w = __ldg(&W4[k * 32 + cr]);
        float a0 = As[(rr * 4 + 0) * 128 + k];
        float a1 = As[(rr * 4 + 1) * 128 + k];
        float a2 = As[(rr * 4 + 2) * 128 + k];
        float a3 = As[(rr * 4 + 3) * 128 + k];
        acc[0][0] += a0 * w.x; acc[0][1] += a0 * w.y; acc[0][2] += a0 * w.z; acc[0][3] += a0 * w.w;
        acc[1][0] += a1 * w.x; acc[1][1] += a1 * w.y; acc[1][2] += a1 * w.z; acc[1][3] += a1 * w.w;
        acc[2][0] += a2 * w.x; acc[2][1] += a2 * w.y; acc[2][2] += a2 * w.z; acc[2][3] += a2 * w.w;
        acc[3][0] += a3 * w.x; acc[3][1] += a3 * w.y; acc[3][2] += a3 * w.z; acc[3][3] += a3 * w.w;
    }

    // s[row] = (h2_row + b) . agg_w
    float4 bv = __ldg(&((const float4*)b)[cr]);
    float4 aw = __ldg(&((const float4*)agg_w)[cr]);
    #pragma unroll
    for (int r = 0; r < 4; r++) {
        float part = (acc[r][0] + bv.x) * aw.x + (acc[r][1] + bv.y) * aw.y
                   + (acc[r][2] + bv.z) * aw.z + (acc[r][3] + bv.w) * aw.w;
        atomicAdd(&s_sm[rr * 4 + r], part);
    }
    __syncthreads();

    // z1[j] += sum_r (s[row]+agg_b) * d1_w[row*100 + j]
    float ab = __ldg(agg_b);
    if (t < 100) {
        float zacc = 0.f;
        for (int r = 0; r < rows; r++) {
            int row = block_row + r;
            zacc += (s_sm[r] + ab) * __ldg(&d1_w[(size_t)row * 100 + t]);
        }
        atomicAdd(&g_z1[t], zacc);
    }
}

// ---------------- K10: tiny MLP tail ----------------
__global__ void k_tail(const float* __restrict__ d1_b,
                       const float* __restrict__ d2_w, const float* __restrict__ d2_b,
                       const float* __restrict__ d3_w, const float* __restrict__ d3_b,
                       float* __restrict__ out) {
    __shared__ float a[100];
    __shared__ float z2[20];
    int t = threadIdx.x;
    if (t < 100) a[t] = g_z1[t] + d1_b[t];
    __syncthreads();
    if (t < 20) {
        float s = d2_b[t];
        #pragma unroll 4
        for (int j = 0; j < 100; j++) s += a[j] * d2_w[j * 20 + t];
        z2[t] = s >= 0.f ? s : 0.01f * s;
    }
    __syncthreads();
    if (t < 10) {
        float s = d3_b[t];
        #pragma unroll
        for (int m = 0; m < 20; m++) s += z2[m] * d3_w[m * 10 + t];
        out[t] = s;
    }
}

// ---------------- launch ----------------
extern "C" void kernel_launch(void* const* d_in, const int* in_sizes, int n_in,
                              void* d_out, int out_size) {
    const float* x     = (const float*)d_in[0];
    const int*   src   = (const int*)d_in[1];
    const int*   dst   = (const int*)d_in[2];
    const float* W1    = (const float*)d_in[3];
    const float* b1    = (const float*)d_in[4];
    const float* W2    = (const float*)d_in[5];
    const float* b2    = (const float*)d_in[6];
    const float* agg_w = (const float*)d_in[7];
    const float* agg_b = (const float*)d_in[8];
    const float* d1_w  = (const float*)d_in[9];
    const float* d1_b  = (const float*)d_in[10];
    const float* d2_w  = (const float*)d_in[11];
    const float* d2_b  = (const float*)d_in[12];
    const float* d3_w  = (const float*)d_in[13];
    const float* d3_b  = (const float*)d_in[14];

    int nodes = in_sizes[0] / DD;
    int E = in_sizes[1];
    float* out = (float*)d_out;

    int gb = (nodes + 31) / 32;            // GEMM blocks (32 rows each)
    int gw = (nodes + 7) / 8;              // gather blocks (8 warps each)

    k_zero<<<(nodes + 255) / 256, 256>>>(nodes);
    k_degree<<<1024, 256>>>(src, dst, E);
    k_scan<<<1, 1024>>>(nodes);
    k_fill<<<1024, 256>>>(src, dst, E);
    k_prescale<<<1024, 256>>>((const float4*)x, nodes);
    k_gather<<<gw, 256>>>(0, nodes);
    k_gemm1<<<gb, 256>>>(W1, b1, nodes);
    k_gather<<<gw, 256>>>(1, nodes);
    k_gemm2_head<<<gb, 256>>>(W2, b2, agg_w, agg_b, d1_w, nodes);
    k_tail<<<1, 128>>>(d1_b, d2_w, d2_b, d3_w, d3_b, out);
}